// round 2
// baseline (speedup 1.0000x reference)
#include <cuda_runtime.h>
#include <cuda_bf16.h>
#include <cstdint>

// Problem constants
constexpr int B    = 32;
constexpr int H    = 1024;
constexpr int MEL  = 128;
constexpr int TENC = 512;
constexpr int TMEL = 400;
constexpr int H4   = H / 4;     // 256
constexpr int TE4  = TENC / 4;

// Output layout: masked_mel [B,TMEL,MEL] | masked_gate [B,TMEL] | mask [B,TMEL]
constexpr size_t OFF_GATE = (size_t)B * TMEL * MEL;
constexpr size_t OFF_MASK = OFF_GATE + (size_t)B * TMEL;

// ---------------- device scratch (static: no allocations allowed) ----------
__device__ float g_energy[(size_t)B * TENC * H];   // 67 MB
__device__ float g_h0[2][B * H];
__device__ float g_h1[2][B * H];
__device__ float g_decin[B * MEL];
__device__ float g_scores[B * TENC];
__device__ float g_ctx[B * H];
__device__ float g_co[B * H];

__device__ unsigned g_bar_arrive = 0;
__device__ volatile unsigned g_bar_gen = 0;

// ---------------- helpers ---------------------------------------------------
__device__ __forceinline__ float wsum(float v) {
    v += __shfl_xor_sync(0xffffffffu, v, 16);
    v += __shfl_xor_sync(0xffffffffu, v, 8);
    v += __shfl_xor_sync(0xffffffffu, v, 4);
    v += __shfl_xor_sync(0xffffffffu, v, 2);
    v += __shfl_xor_sync(0xffffffffu, v, 1);
    return v;
}
__device__ __forceinline__ float wmax(float v) {
    v = fmaxf(v, __shfl_xor_sync(0xffffffffu, v, 16));
    v = fmaxf(v, __shfl_xor_sync(0xffffffffu, v, 8));
    v = fmaxf(v, __shfl_xor_sync(0xffffffffu, v, 4));
    v = fmaxf(v, __shfl_xor_sync(0xffffffffu, v, 2));
    v = fmaxf(v, __shfl_xor_sync(0xffffffffu, v, 1));
    return v;
}
__device__ __forceinline__ float dot4(float4 a, float4 b, float acc) {
    acc = fmaf(a.x, b.x, acc);
    acc = fmaf(a.y, b.y, acc);
    acc = fmaf(a.z, b.z, acc);
    acc = fmaf(a.w, b.w, acc);
    return acc;
}
__device__ __forceinline__ float sigmoidf_(float x) {
    return 1.f / (1.f + expf(-x));
}

// Grid-wide barrier: sense-reversing generation counter. Safe because grid ==
// #SMs and each SM holds exactly one resident block (256 thr, no smem).
__device__ __forceinline__ void grid_barrier(int nblk) {
    __syncthreads();
    if (threadIdx.x == 0) {
        __threadfence();                       // release my phase's writes
        unsigned gen = g_bar_gen;
        if (atomicAdd(&g_bar_arrive, 1u) == (unsigned)nblk - 1u) {
            g_bar_arrive = 0;
            __threadfence();
            g_bar_gen = gen + 1u;
        } else {
            while (g_bar_gen == gen) { __nanosleep(64); }
        }
        __threadfence();                       // acquire others' writes
    }
    __syncthreads();
}

// ---------------- phase: GRU cell (warp job = (column j, batch half)) ------
__device__ void gru_phase(int gw, int GW, int lane,
                          const float* __restrict__ x, int XD,
                          const float* __restrict__ hprev,
                          float* __restrict__ hnew,
                          const float* __restrict__ Wih,
                          const float* __restrict__ Whh,
                          const float* __restrict__ bih,
                          const float* __restrict__ bhh) {
    const int XD4 = XD >> 2;
    for (int job = gw; job < 2 * H; job += GW) {
        const int j  = job >> 1;
        const int b0 = (job & 1) << 4;
        float ar[16], az[16], ani[16], anh[16];
#pragma unroll
        for (int i = 0; i < 16; ++i) { ar[i] = 0.f; az[i] = 0.f; ani[i] = 0.f; anh[i] = 0.f; }

        // input-gate dots (length XD)
        {
            const float4* wr = reinterpret_cast<const float4*>(Wih + (size_t)j * XD);
            const float4* wz = reinterpret_cast<const float4*>(Wih + (size_t)(H + j) * XD);
            const float4* wn = reinterpret_cast<const float4*>(Wih + (size_t)(2 * H + j) * XD);
            const float4* x4 = reinterpret_cast<const float4*>(x);
            for (int k = lane; k < XD4; k += 32) {
                float4 r4 = wr[k], z4 = wz[k], n4 = wn[k];
#pragma unroll
                for (int bb = 0; bb < 16; ++bb) {
                    float4 xv = x4[(size_t)(b0 + bb) * XD4 + k];
                    ar[bb]  = dot4(r4, xv, ar[bb]);
                    az[bb]  = dot4(z4, xv, az[bb]);
                    ani[bb] = dot4(n4, xv, ani[bb]);
                }
            }
        }
        // hidden-gate dots (length H)
        {
            const float4* wr = reinterpret_cast<const float4*>(Whh + (size_t)j * H);
            const float4* wz = reinterpret_cast<const float4*>(Whh + (size_t)(H + j) * H);
            const float4* wn = reinterpret_cast<const float4*>(Whh + (size_t)(2 * H + j) * H);
            const float4* h4 = reinterpret_cast<const float4*>(hprev);
            for (int k = lane; k < H4; k += 32) {
                float4 r4 = wr[k], z4 = wz[k], n4 = wn[k];
#pragma unroll
                for (int bb = 0; bb < 16; ++bb) {
                    float4 hv = h4[(size_t)(b0 + bb) * H4 + k];
                    ar[bb]  = dot4(r4, hv, ar[bb]);
                    az[bb]  = dot4(z4, hv, az[bb]);
                    anh[bb] = dot4(n4, hv, anh[bb]);
                }
            }
        }
        const float br  = bih[j] + bhh[j];
        const float bz  = bih[H + j] + bhh[H + j];
        const float bni = bih[2 * H + j];
        const float bnh = bhh[2 * H + j];
#pragma unroll
        for (int bb = 0; bb < 16; ++bb) {
            float r  = wsum(ar[bb]) + br;
            float z  = wsum(az[bb]) + bz;
            float ni = wsum(ani[bb]) + bni;
            float nh = wsum(anh[bb]) + bnh;
            if (lane == bb) {
                float rr = sigmoidf_(r);
                float zz = sigmoidf_(z);
                float nn = tanhf(ni + rr * nh);
                const int idx = (b0 + bb) * H + j;
                hnew[idx] = (1.f - zz) * nn + zz * hprev[idx];
            }
        }
    }
}

// ---------------- main persistent kernel ------------------------------------
__global__ void __launch_bounds__(256, 1)
decoder_kernel(const float* __restrict__ enc_hidden,
               const float* __restrict__ enc_out,
               const int*   __restrict__ lens,
               const float* __restrict__ W_attn, const float* __restrict__ b_attn,
               const float* __restrict__ Wih0, const float* __restrict__ Whh0,
               const float* __restrict__ bih0, const float* __restrict__ bhh0,
               const float* __restrict__ Wih1, const float* __restrict__ Whh1,
               const float* __restrict__ bih1, const float* __restrict__ bhh1,
               const float* __restrict__ Wc,   const float* __restrict__ bc,
               const float* __restrict__ Wp,   const float* __restrict__ bp,
               const float* __restrict__ Wg,   const float* __restrict__ bg,
               float* __restrict__ out, int nblk) {
    const int lane = threadIdx.x & 31;
    const int wid  = threadIdx.x >> 5;
    const int gw   = blockIdx.x * (blockDim.x >> 5) + wid;
    const int GW   = nblk * (blockDim.x >> 5);
    const int gtid = blockIdx.x * blockDim.x + threadIdx.x;
    const int gsz  = nblk * blockDim.x;

    // ---- init: states, dec_in, mask output ----
    for (int i = gtid; i < B * H; i += gsz) {
        g_h0[0][i] = enc_hidden[i];
        g_h1[0][i] = enc_hidden[B * H + i];
    }
    for (int i = gtid; i < B * MEL; i += gsz) g_decin[i] = 0.f;
    for (int i = gtid; i < B * TMEL; i += gsz) {
        int b = i / TMEL, t = i - b * TMEL;
        out[OFF_MASK + i] = (t > lens[b]) ? 1.f : 0.f;
    }

    // ---- one-time: energy[b,t,j] = enc[b,t,:] . W_attn[j,:] + b_attn[j] ----
    // warp job = (column j, 16-row bt chunk); 1M jobs
    {
        const float4* e4 = reinterpret_cast<const float4*>(enc_out);
        for (int job = gw; job < (1 << 20); job += GW) {
            const int j   = job & (H - 1);
            const int bt0 = (job >> 10) << 4;
            float acc[16];
#pragma unroll
            for (int i = 0; i < 16; ++i) acc[i] = 0.f;
            const float4* wa = reinterpret_cast<const float4*>(W_attn + (size_t)j * H);
            for (int k = lane; k < H4; k += 32) {
                float4 wv = wa[k];
#pragma unroll
                for (int bb = 0; bb < 16; ++bb) {
                    float4 ev = e4[(size_t)(bt0 + bb) * H4 + k];
                    acc[bb] = dot4(wv, ev, acc[bb]);
                }
            }
            const float bav = b_attn[j];
#pragma unroll
            for (int bb = 0; bb < 16; ++bb) {
                float s = wsum(acc[bb]);
                if (lane == bb) g_energy[(size_t)(bt0 + bb) * H + j] = s + bav;
            }
        }
    }
    grid_barrier(nblk);

    // ---- 400 autoregressive steps ----
    for (int step = 0; step < TMEL; ++step) {
        const int cur = step & 1, nxt = cur ^ 1;

        // P1: GRU layer 0
        gru_phase(gw, GW, lane, g_decin, MEL, g_h0[cur], g_h0[nxt],
                  Wih0, Whh0, bih0, bhh0);
        grid_barrier(nblk);

        // P2: GRU layer 1
        gru_phase(gw, GW, lane, g_h0[nxt], H, g_h1[cur], g_h1[nxt],
                  Wih1, Whh1, bih1, bhh1);
        grid_barrier(nblk);

        // P3: scores[b,t] = h1 . energy[b,t,:]   (warp job = (b, 8 t's))
        {
            const float* h1n = g_h1[nxt];
            for (int job = gw; job < B * (TENC / 8); job += GW) {
                const int b  = job >> 6;
                const int t0 = (job & 63) << 3;
                float acc[8];
#pragma unroll
                for (int i = 0; i < 8; ++i) acc[i] = 0.f;
                const float4* hb = reinterpret_cast<const float4*>(h1n + (size_t)b * H);
                const float4* Eb = reinterpret_cast<const float4*>(
                    g_energy + ((size_t)b * TENC + t0) * H);
                for (int k = lane; k < H4; k += 32) {
                    float4 hv = hb[k];
#pragma unroll
                    for (int i = 0; i < 8; ++i) {
                        float4 ev = Eb[(size_t)i * H4 + k];
                        acc[i] = dot4(hv, ev, acc[i]);
                    }
                }
#pragma unroll
                for (int i = 0; i < 8; ++i) {
                    float s = wsum(acc[i]);
                    if (lane == i) g_scores[b * TENC + t0 + i] = s;
                }
            }
        }
        grid_barrier(nblk);

        // P4: softmax (recomputed per warp) + context
        // warp job = (b, 128-wide h chunk); lane owns 4 h's (float4)
        {
            for (int job = gw; job < B * (H / 128); job += GW) {
                const int b   = job >> 3;
                const int h0c = (job & 7) << 7;
                // stable softmax over scores[b][:]
                float sc[16];
                const float* srow = g_scores + b * TENC;
                float mx = -1e30f;
#pragma unroll
                for (int i = 0; i < 16; ++i) {
                    sc[i] = srow[i * 32 + lane];
                    mx = fmaxf(mx, sc[i]);
                }
                mx = wmax(mx);
                float sm = 0.f;
#pragma unroll
                for (int i = 0; i < 16; ++i) { sc[i] = expf(sc[i] - mx); sm += sc[i]; }
                sm = wsum(sm);
                const float inv = 1.f / sm;
#pragma unroll
                for (int i = 0; i < 16; ++i) sc[i] *= inv;

                float4 acc = make_float4(0.f, 0.f, 0.f, 0.f);
                const float4* encb = reinterpret_cast<const float4*>(
                    enc_out + (size_t)b * TENC * H + h0c);
#pragma unroll
                for (int i = 0; i < 16; ++i) {
                    float scv = sc[i];
                    for (int tt = 0; tt < 32; ++tt) {
                        float p = __shfl_sync(0xffffffffu, scv, tt);
                        float4 ev = encb[(size_t)(i * 32 + tt) * H4 + lane];
                        acc.x = fmaf(p, ev.x, acc.x);
                        acc.y = fmaf(p, ev.y, acc.y);
                        acc.z = fmaf(p, ev.z, acc.z);
                        acc.w = fmaf(p, ev.w, acc.w);
                    }
                }
                reinterpret_cast<float4*>(g_ctx + (size_t)b * H + h0c)[lane] = acc;
            }
        }
        grid_barrier(nblk);

        // P5: co = tanh([h1, ctx] @ Wc^T + bc)   (warp job = (j, batch half))
        {
            const float* h1n = g_h1[nxt];
            for (int job = gw; job < 2 * H; job += GW) {
                const int j  = job >> 1;
                const int b0 = (job & 1) << 4;
                float acc[16];
#pragma unroll
                for (int i = 0; i < 16; ++i) acc[i] = 0.f;
                const float4* w1 = reinterpret_cast<const float4*>(Wc + (size_t)j * 2 * H);
                const float4* w2 = w1 + H4;
                const float4* h4 = reinterpret_cast<const float4*>(h1n);
                const float4* c4 = reinterpret_cast<const float4*>(g_ctx);
                for (int k = lane; k < H4; k += 32) {
                    float4 wv = w1[k];
#pragma unroll
                    for (int bb = 0; bb < 16; ++bb)
                        acc[bb] = dot4(wv, h4[(size_t)(b0 + bb) * H4 + k], acc[bb]);
                }
                for (int k = lane; k < H4; k += 32) {
                    float4 wv = w2[k];
#pragma unroll
                    for (int bb = 0; bb < 16; ++bb)
                        acc[bb] = dot4(wv, c4[(size_t)(b0 + bb) * H4 + k], acc[bb]);
                }
                const float bcv = bc[j];
#pragma unroll
                for (int bb = 0; bb < 16; ++bb) {
                    float s = wsum(acc[bb]);
                    if (lane == bb) g_co[(b0 + bb) * H + j] = tanhf(s + bcv);
                }
            }
        }
        grid_barrier(nblk);

        // P6: mel = co @ Wp^T + bp ; gate = co @ Wg^T + bg ; write outputs
        {
            const float4* co4 = reinterpret_cast<const float4*>(g_co);
            for (int job = gw; job < 2 * MEL + 2; job += GW) {
                if (job < 2 * MEL) {
                    const int m  = job >> 1;
                    const int b0 = (job & 1) << 4;
                    float acc[16];
#pragma unroll
                    for (int i = 0; i < 16; ++i) acc[i] = 0.f;
                    const float4* wp = reinterpret_cast<const float4*>(Wp + (size_t)m * H);
                    for (int k = lane; k < H4; k += 32) {
                        float4 wv = wp[k];
#pragma unroll
                        for (int bb = 0; bb < 16; ++bb)
                            acc[bb] = dot4(wv, co4[(size_t)(b0 + bb) * H4 + k], acc[bb]);
                    }
                    const float bpv = bp[m];
#pragma unroll
                    for (int bb = 0; bb < 16; ++bb) {
                        float s = wsum(acc[bb]);
                        if (lane == bb) {
                            const int b = b0 + bb;
                            const float val = s + bpv;
                            g_decin[b * MEL + m] = val;   // next-step input (pre-mask)
                            const bool msk = step > lens[b];
                            out[((size_t)b * TMEL + step) * MEL + m] = msk ? 0.f : val;
                        }
                    }
                } else {
                    const int b0 = (job - 2 * MEL) << 4;
                    float acc[16];
#pragma unroll
                    for (int i = 0; i < 16; ++i) acc[i] = 0.f;
                    const float4* wg = reinterpret_cast<const float4*>(Wg);
                    for (int k = lane; k < H4; k += 32) {
                        float4 wv = wg[k];
#pragma unroll
                        for (int bb = 0; bb < 16; ++bb)
                            acc[bb] = dot4(wv, co4[(size_t)(b0 + bb) * H4 + k], acc[bb]);
                    }
#pragma unroll
                    for (int bb = 0; bb < 16; ++bb) {
                        float s = wsum(acc[bb]);
                        if (lane == bb) {
                            const int b = b0 + bb;
                            const float g = s + bg[0];
                            const bool msk = step > lens[b];
                            out[OFF_GATE + (size_t)b * TMEL + step] = msk ? 1000.f : g;
                        }
                    }
                }
            }
        }
        grid_barrier(nblk);
    }
}

// ---------------- host launch ------------------------------------------------
extern "C" void kernel_launch(void* const* d_in, const int* in_sizes, int n_in,
                              void* d_out, int out_size) {
    (void)in_sizes; (void)n_in; (void)out_size;
    int dev = 0;
    cudaGetDevice(&dev);
    int sms = 0;
    cudaDeviceGetAttribute(&sms, cudaDevAttrMultiProcessorCount, dev);
    if (sms <= 0) sms = 148;

    decoder_kernel<<<sms, 256>>>(
        (const float*)d_in[0],   // encoder_hidden [4,B,H]
        (const float*)d_in[1],   // encoder_outputs [B,TENC,H]
        (const int*)d_in[3],     // mel_spec_lens [B]   (d_in[2] = y, unused)
        (const float*)d_in[4],  (const float*)d_in[5],    // W_attn, b_attn
        (const float*)d_in[6],  (const float*)d_in[7],    // W_ih0, W_hh0
        (const float*)d_in[8],  (const float*)d_in[9],    // b_ih0, b_hh0
        (const float*)d_in[10], (const float*)d_in[11],   // W_ih1, W_hh1
        (const float*)d_in[12], (const float*)d_in[13],   // b_ih1, b_hh1
        (const float*)d_in[14], (const float*)d_in[15],   // Wc, bc
        (const float*)d_in[16], (const float*)d_in[17],   // Wp, bp
        (const float*)d_in[18], (const float*)d_in[19],   // Wg, bg
        (float*)d_out, sms);
}

// round 3
// speedup vs baseline: 1.2270x; 1.2270x over previous
#include <cuda_runtime.h>
#include <cuda_bf16.h>
#include <cstdint>

// Problem constants
constexpr int B    = 32;
constexpr int H    = 1024;
constexpr int MEL  = 128;
constexpr int TENC = 512;
constexpr int TMEL = 400;
constexpr int H4   = H / 4;     // 256

// Output layout: masked_mel [B,TMEL,MEL] | masked_gate [B,TMEL] | mask [B,TMEL]
constexpr size_t OFF_GATE = (size_t)B * TMEL * MEL;
constexpr size_t OFF_MASK = OFF_GATE + (size_t)B * TMEL;

// ---------------- device scratch (static: no allocations allowed) ----------
__device__ float g_WT[(size_t)H * H];       // W_attn transposed [k][j], 4 MB
__device__ float g_h0[2][B * H];
__device__ float g_h1[2][B * H];
__device__ float g_decin[B * MEL];
__device__ float g_r[B * H];
__device__ float g_z[B * H];
__device__ float g_v[B * H];
__device__ float g_scores[B * TENC];
__device__ float g_ctxp[4][B * H];          // partial contexts (t-slices)
__device__ float g_ctx[B * H];
__device__ float g_co[B * H];

__device__ unsigned g_bar_arrive = 0;
__device__ volatile unsigned g_bar_gen = 0;

// ---------------- helpers ---------------------------------------------------
__device__ __forceinline__ float wsum(float v) {
    v += __shfl_xor_sync(0xffffffffu, v, 16);
    v += __shfl_xor_sync(0xffffffffu, v, 8);
    v += __shfl_xor_sync(0xffffffffu, v, 4);
    v += __shfl_xor_sync(0xffffffffu, v, 2);
    v += __shfl_xor_sync(0xffffffffu, v, 1);
    return v;
}
__device__ __forceinline__ float wmax(float v) {
    v = fmaxf(v, __shfl_xor_sync(0xffffffffu, v, 16));
    v = fmaxf(v, __shfl_xor_sync(0xffffffffu, v, 8));
    v = fmaxf(v, __shfl_xor_sync(0xffffffffu, v, 4));
    v = fmaxf(v, __shfl_xor_sync(0xffffffffu, v, 2));
    v = fmaxf(v, __shfl_xor_sync(0xffffffffu, v, 1));
    return v;
}
__device__ __forceinline__ float dot4(float4 a, float4 b, float acc) {
    acc = fmaf(a.x, b.x, acc);
    acc = fmaf(a.y, b.y, acc);
    acc = fmaf(a.z, b.z, acc);
    acc = fmaf(a.w, b.w, acc);
    return acc;
}
__device__ __forceinline__ float sigmoidf_(float x) {
    return 1.f / (1.f + expf(-x));
}

// Grid-wide barrier (1 resident block per SM guaranteed: 512 thr, 128 regs, no smem)
__device__ __forceinline__ void grid_barrier(int nblk) {
    __syncthreads();
    if (threadIdx.x == 0) {
        __threadfence();
        unsigned gen = g_bar_gen;
        if (atomicAdd(&g_bar_arrive, 1u) == (unsigned)nblk - 1u) {
            g_bar_arrive = 0;
            __threadfence();
            g_bar_gen = gen + 1u;
        } else {
            while (g_bar_gen == gen) { __nanosleep(32); }
        }
        __threadfence();
    }
    __syncthreads();
}

// ---------------- GRU sub-phase A: r and z gates ----------------------------
__device__ void gru_rz(int gw, int GW, int lane,
                       const float* __restrict__ x, int XD,
                       const float* __restrict__ hprev,
                       const float* __restrict__ Wih,
                       const float* __restrict__ Whh,
                       const float* __restrict__ bih,
                       const float* __restrict__ bhh) {
    const int XD4 = XD >> 2;
    for (int job = gw; job < 2 * H; job += GW) {
        const int j  = job >> 1;
        const int b0 = (job & 1) << 4;
        float ar[16], az[16];
#pragma unroll
        for (int i = 0; i < 16; ++i) { ar[i] = 0.f; az[i] = 0.f; }
        {   // input dots
            const float4* wr = reinterpret_cast<const float4*>(Wih + (size_t)j * XD);
            const float4* wz = reinterpret_cast<const float4*>(Wih + (size_t)(H + j) * XD);
            const float4* x4 = reinterpret_cast<const float4*>(x);
            for (int k = lane; k < XD4; k += 32) {
                float4 r4 = wr[k], z4 = wz[k];
#pragma unroll
                for (int bb = 0; bb < 16; ++bb) {
                    float4 xv = x4[(size_t)(b0 + bb) * XD4 + k];
                    ar[bb] = dot4(r4, xv, ar[bb]);
                    az[bb] = dot4(z4, xv, az[bb]);
                }
            }
        }
        {   // hidden dots
            const float4* wr = reinterpret_cast<const float4*>(Whh + (size_t)j * H);
            const float4* wz = reinterpret_cast<const float4*>(Whh + (size_t)(H + j) * H);
            const float4* h4 = reinterpret_cast<const float4*>(hprev);
            for (int k = lane; k < H4; k += 32) {
                float4 r4 = wr[k], z4 = wz[k];
#pragma unroll
                for (int bb = 0; bb < 16; ++bb) {
                    float4 hv = h4[(size_t)(b0 + bb) * H4 + k];
                    ar[bb] = dot4(r4, hv, ar[bb]);
                    az[bb] = dot4(z4, hv, az[bb]);
                }
            }
        }
        const float br = bih[j] + bhh[j];
        const float bz = bih[H + j] + bhh[H + j];
#pragma unroll
        for (int bb = 0; bb < 16; ++bb) {
            float r = wsum(ar[bb]) + br;
            float z = wsum(az[bb]) + bz;
            if (lane == bb) {
                const int idx = (b0 + bb) * H + j;
                g_r[idx] = sigmoidf_(r);
                g_z[idx] = sigmoidf_(z);
            }
        }
    }
}

// ---------------- GRU sub-phase B: n gate + combine --------------------------
__device__ void gru_n(int gw, int GW, int lane,
                      const float* __restrict__ x, int XD,
                      const float* __restrict__ hprev,
                      float* __restrict__ hnew,
                      const float* __restrict__ Wih,
                      const float* __restrict__ Whh,
                      const float* __restrict__ bih,
                      const float* __restrict__ bhh) {
    const int XD4 = XD >> 2;
    for (int job = gw; job < 2 * H; job += GW) {
        const int j  = job >> 1;
        const int b0 = (job & 1) << 4;
        float ani[16], anh[16];
#pragma unroll
        for (int i = 0; i < 16; ++i) { ani[i] = 0.f; anh[i] = 0.f; }
        {
            const float4* wn = reinterpret_cast<const float4*>(Wih + (size_t)(2 * H + j) * XD);
            const float4* x4 = reinterpret_cast<const float4*>(x);
            for (int k = lane; k < XD4; k += 32) {
                float4 n4 = wn[k];
#pragma unroll
                for (int bb = 0; bb < 16; ++bb)
                    ani[bb] = dot4(n4, x4[(size_t)(b0 + bb) * XD4 + k], ani[bb]);
            }
        }
        {
            const float4* wn = reinterpret_cast<const float4*>(Whh + (size_t)(2 * H + j) * H);
            const float4* h4 = reinterpret_cast<const float4*>(hprev);
            for (int k = lane; k < H4; k += 32) {
                float4 n4 = wn[k];
#pragma unroll
                for (int bb = 0; bb < 16; ++bb)
                    anh[bb] = dot4(n4, h4[(size_t)(b0 + bb) * H4 + k], anh[bb]);
            }
        }
        const float bni = bih[2 * H + j];
        const float bnh = bhh[2 * H + j];
#pragma unroll
        for (int bb = 0; bb < 16; ++bb) {
            float ni = wsum(ani[bb]) + bni;
            float nh = wsum(anh[bb]) + bnh;
            if (lane == bb) {
                const int idx = (b0 + bb) * H + j;
                float r = g_r[idx], z = g_z[idx];
                float n = tanhf(ni + r * nh);
                hnew[idx] = (1.f - z) * n + z * hprev[idx];
            }
        }
    }
}

// ---------------- main persistent kernel ------------------------------------
__global__ void __launch_bounds__(512, 1)
decoder_kernel(const float* __restrict__ enc_hidden,
               const float* __restrict__ enc_out,
               const int*   __restrict__ lens,
               const float* __restrict__ W_attn, const float* __restrict__ b_attn,
               const float* __restrict__ Wih0, const float* __restrict__ Whh0,
               const float* __restrict__ bih0, const float* __restrict__ bhh0,
               const float* __restrict__ Wih1, const float* __restrict__ Whh1,
               const float* __restrict__ bih1, const float* __restrict__ bhh1,
               const float* __restrict__ Wc,   const float* __restrict__ bc,
               const float* __restrict__ Wp,   const float* __restrict__ bp,
               const float* __restrict__ Wg,   const float* __restrict__ bg,
               float* __restrict__ out, int nblk) {
    const int lane = threadIdx.x & 31;
    const int wid  = threadIdx.x >> 5;
    const int gw   = blockIdx.x * (blockDim.x >> 5) + wid;
    const int GW   = nblk * (blockDim.x >> 5);
    const int gtid = blockIdx.x * blockDim.x + threadIdx.x;
    const int gsz  = nblk * blockDim.x;

    // ---- init: states, dec_in, mask output, W_attn transpose ----
    for (int i = gtid; i < B * H; i += gsz) {
        g_h0[0][i] = enc_hidden[i];
        g_h1[0][i] = enc_hidden[B * H + i];
    }
    for (int i = gtid; i < B * MEL; i += gsz) g_decin[i] = 0.f;
    for (int i = gtid; i < B * TMEL; i += gsz) {
        int b = i / TMEL, t = i - b * TMEL;
        out[OFF_MASK + i] = (t > lens[b]) ? 1.f : 0.f;
    }
    for (int i = gtid; i < H * H; i += gsz) {
        int k = i >> 10, j = i & (H - 1);
        g_WT[i] = W_attn[(size_t)j * H + k];
    }
    grid_barrier(nblk);

    // ---- 400 autoregressive steps ----
    for (int step = 0; step < TMEL; ++step) {
        const int cur = step & 1, nxt = cur ^ 1;

        // P1a/P1b: GRU layer 0
        gru_rz(gw, GW, lane, g_decin, MEL, g_h0[cur], Wih0, Whh0, bih0, bhh0);
        grid_barrier(nblk);
        gru_n(gw, GW, lane, g_decin, MEL, g_h0[cur], g_h0[nxt], Wih0, Whh0, bih0, bhh0);
        grid_barrier(nblk);

        // P2a/P2b: GRU layer 1
        gru_rz(gw, GW, lane, g_h0[nxt], H, g_h1[cur], Wih1, Whh1, bih1, bhh1);
        grid_barrier(nblk);
        gru_n(gw, GW, lane, g_h0[nxt], H, g_h1[cur], g_h1[nxt], Wih1, Whh1, bih1, bhh1);
        grid_barrier(nblk);

        const float* h1n = g_h1[nxt];

        // Pv: v[b,k] = sum_j W_attn[j,k] * h1[b,j]   (softmax-invariant bias dropped)
        {
            for (int job = gw; job < 2 * H; job += GW) {
                const int col = job >> 1;
                const int b0  = (job & 1) << 4;
                float acc[16];
#pragma unroll
                for (int i = 0; i < 16; ++i) acc[i] = 0.f;
                const float4* wk = reinterpret_cast<const float4*>(g_WT + (size_t)col * H);
                const float4* h4 = reinterpret_cast<const float4*>(h1n);
                for (int k = lane; k < H4; k += 32) {
                    float4 wv = wk[k];
#pragma unroll
                    for (int bb = 0; bb < 16; ++bb)
                        acc[bb] = dot4(wv, h4[(size_t)(b0 + bb) * H4 + k], acc[bb]);
                }
#pragma unroll
                for (int bb = 0; bb < 16; ++bb) {
                    float s = wsum(acc[bb]);
                    if (lane == bb) g_v[(b0 + bb) * H + col] = s;
                }
            }
        }
        grid_barrier(nblk);

        // P3: scores[b,t] = v[b,:] . enc_out[b,t,:]   (warp job = (b, 8 t's))
        {
            for (int job = gw; job < B * (TENC / 8); job += GW) {
                const int b  = job >> 6;
                const int t0 = (job & 63) << 3;
                float acc[8];
#pragma unroll
                for (int i = 0; i < 8; ++i) acc[i] = 0.f;
                const float4* vb = reinterpret_cast<const float4*>(g_v + (size_t)b * H);
                const float4* Eb = reinterpret_cast<const float4*>(
                    enc_out + ((size_t)b * TENC + t0) * H);
                for (int k = lane; k < H4; k += 32) {
                    float4 hv = vb[k];
#pragma unroll
                    for (int i = 0; i < 8; ++i)
                        acc[i] = dot4(hv, Eb[(size_t)i * H4 + k], acc[i]);
                }
#pragma unroll
                for (int i = 0; i < 8; ++i) {
                    float s = wsum(acc[i]);
                    if (lane == i) g_scores[b * TENC + t0 + i] = s;
                }
            }
        }
        grid_barrier(nblk);

        // P4: softmax (recomputed per warp) + partial context over t-slice
        // job = (b, h-chunk of 128, t-slice of 128): 1024 jobs
        {
            for (int job = gw; job < B * 8 * 4; job += GW) {
                const int b  = job >> 5;
                const int hc = (job >> 2) & 7;
                const int s  = job & 3;
                float sc[16];
                const float* srow = g_scores + b * TENC;
                float mx = -1e30f;
#pragma unroll
                for (int i = 0; i < 16; ++i) {
                    sc[i] = srow[i * 32 + lane];
                    mx = fmaxf(mx, sc[i]);
                }
                mx = wmax(mx);
                float sm = 0.f;
#pragma unroll
                for (int i = 0; i < 16; ++i) { sc[i] = expf(sc[i] - mx); sm += sc[i]; }
                sm = wsum(sm);
                const float inv = 1.f / sm;

                float4 acc = make_float4(0.f, 0.f, 0.f, 0.f);
                const float4* encb = reinterpret_cast<const float4*>(enc_out)
                                   + (size_t)b * TENC * H4 + hc * 32 + lane;
#pragma unroll
                for (int i = 4 * 0; i < 4; ++i) {
                    const int ii = s * 4 + i;
                    float scv = sc[ii] * inv;
                    for (int tt = 0; tt < 32; ++tt) {
                        float p = __shfl_sync(0xffffffffu, scv, tt);
                        float4 ev = encb[(size_t)(ii * 32 + tt) * H4];
                        acc.x = fmaf(p, ev.x, acc.x);
                        acc.y = fmaf(p, ev.y, acc.y);
                        acc.z = fmaf(p, ev.z, acc.z);
                        acc.w = fmaf(p, ev.w, acc.w);
                    }
                }
                reinterpret_cast<float4*>(g_ctxp[s] + (size_t)b * H + hc * 128)[lane] = acc;
            }
        }
        grid_barrier(nblk);

        // P4.5: sum the 4 context slices
        for (int i = gtid; i < B * H; i += gsz)
            g_ctx[i] = (g_ctxp[0][i] + g_ctxp[1][i]) + (g_ctxp[2][i] + g_ctxp[3][i]);
        grid_barrier(nblk);

        // P5: co = tanh([h1, ctx] @ Wc^T + bc)
        {
            for (int job = gw; job < 2 * H; job += GW) {
                const int j  = job >> 1;
                const int b0 = (job & 1) << 4;
                float acc[16];
#pragma unroll
                for (int i = 0; i < 16; ++i) acc[i] = 0.f;
                const float4* w1 = reinterpret_cast<const float4*>(Wc + (size_t)j * 2 * H);
                const float4* w2 = w1 + H4;
                const float4* h4 = reinterpret_cast<const float4*>(h1n);
                const float4* c4 = reinterpret_cast<const float4*>(g_ctx);
                for (int k = lane; k < H4; k += 32) {
                    float4 wv = w1[k];
#pragma unroll
                    for (int bb = 0; bb < 16; ++bb)
                        acc[bb] = dot4(wv, h4[(size_t)(b0 + bb) * H4 + k], acc[bb]);
                }
                for (int k = lane; k < H4; k += 32) {
                    float4 wv = w2[k];
#pragma unroll
                    for (int bb = 0; bb < 16; ++bb)
                        acc[bb] = dot4(wv, c4[(size_t)(b0 + bb) * H4 + k], acc[bb]);
                }
                const float bcv = bc[j];
#pragma unroll
                for (int bb = 0; bb < 16; ++bb) {
                    float s = wsum(acc[bb]);
                    if (lane == bb) g_co[(b0 + bb) * H + j] = tanhf(s + bcv);
                }
            }
        }
        grid_barrier(nblk);

        // P6: mel = co @ Wp^T + bp ; gate = co @ Wg^T + bg ; write outputs
        {
            const float4* co4 = reinterpret_cast<const float4*>(g_co);
            for (int job = gw; job < 2 * MEL + 2; job += GW) {
                if (job < 2 * MEL) {
                    const int m  = job >> 1;
                    const int b0 = (job & 1) << 4;
                    float acc[16];
#pragma unroll
                    for (int i = 0; i < 16; ++i) acc[i] = 0.f;
                    const float4* wp = reinterpret_cast<const float4*>(Wp + (size_t)m * H);
                    for (int k = lane; k < H4; k += 32) {
                        float4 wv = wp[k];
#pragma unroll
                        for (int bb = 0; bb < 16; ++bb)
                            acc[bb] = dot4(wv, co4[(size_t)(b0 + bb) * H4 + k], acc[bb]);
                    }
                    const float bpv = bp[m];
#pragma unroll
                    for (int bb = 0; bb < 16; ++bb) {
                        float s = wsum(acc[bb]);
                        if (lane == bb) {
                            const int b = b0 + bb;
                            const float val = s + bpv;
                            g_decin[b * MEL + m] = val;
                            const bool msk = step > lens[b];
                            out[((size_t)b * TMEL + step) * MEL + m] = msk ? 0.f : val;
                        }
                    }
                } else {
                    const int b0 = (job - 2 * MEL) << 4;
                    float acc[16];
#pragma unroll
                    for (int i = 0; i < 16; ++i) acc[i] = 0.f;
                    const float4* wg = reinterpret_cast<const float4*>(Wg);
                    for (int k = lane; k < H4; k += 32) {
                        float4 wv = wg[k];
#pragma unroll
                        for (int bb = 0; bb < 16; ++bb)
                            acc[bb] = dot4(wv, co4[(size_t)(b0 + bb) * H4 + k], acc[bb]);
                    }
#pragma unroll
                    for (int bb = 0; bb < 16; ++bb) {
                        float s = wsum(acc[bb]);
                        if (lane == bb) {
                            const int b = b0 + bb;
                            const float g = s + bg[0];
                            const bool msk = step > lens[b];
                            out[OFF_GATE + (size_t)b * TMEL + step] = msk ? 1000.f : g;
                        }
                    }
                }
            }
        }
        grid_barrier(nblk);
    }
}

// ---------------- host launch ------------------------------------------------
extern "C" void kernel_launch(void* const* d_in, const int* in_sizes, int n_in,
                              void* d_out, int out_size) {
    (void)in_sizes; (void)n_in; (void)out_size;
    int dev = 0;
    cudaGetDevice(&dev);
    int sms = 0;
    cudaDeviceGetAttribute(&sms, cudaDevAttrMultiProcessorCount, dev);
    if (sms <= 0) sms = 148;

    decoder_kernel<<<sms, 512>>>(
        (const float*)d_in[0],   // encoder_hidden [4,B,H]
        (const float*)d_in[1],   // encoder_outputs [B,TENC,H]
        (const int*)d_in[3],     // mel_spec_lens [B]   (d_in[2] = y, unused)
        (const float*)d_in[4],  (const float*)d_in[5],    // W_attn, b_attn
        (const float*)d_in[6],  (const float*)d_in[7],    // W_ih0, W_hh0
        (const float*)d_in[8],  (const float*)d_in[9],    // b_ih0, b_hh0
        (const float*)d_in[10], (const float*)d_in[11],   // W_ih1, W_hh1
        (const float*)d_in[12], (const float*)d_in[13],   // b_ih1, b_hh1
        (const float*)d_in[14], (const float*)d_in[15],   // Wc, bc
        (const float*)d_in[16], (const float*)d_in[17],   // Wp, bp
        (const float*)d_in[18], (const float*)d_in[19],   // Wg, bg
        (float*)d_out, sms);
}